// round 14
// baseline (speedup 1.0000x reference)
#include <cuda_runtime.h>
#include <cuda_fp16.h>
#include <cstdint>

#define NIMG 256
#define RROOM 32
#define WW 8
#define HH 6
#define MXY 72
#define PIX (MXY*MXY)
#define EMBD 6

__device__ __align__(16) unsigned g_X0h[NIMG*8*PIX];
__device__ __align__(16) unsigned g_XAh[NIMG*32*PIX];   // conv5 out, NHWC (32 half2/px)
__device__ __align__(16) unsigned g_XBw[NIMG*RROOM*80*32]; // layer2 windows [n][r][80px][32pair]
__device__ float g_feat[NIMG*RROOM*64];
__device__ float g_S[NIMG*128];
__device__ float g_wt[122880];
__device__ __align__(16) uint2 g_wp[25088];  // conv5 @0, conv3A @6656, conv3B @15872

__device__ __forceinline__ unsigned f2h2(float lo, float hi) {
    __half2 h = __floats2half2_rn(lo, hi);
    return *reinterpret_cast<unsigned*>(&h);
}
__device__ __forceinline__ void mma_f16(float d[4], const unsigned a[4], unsigned b0, unsigned b1) {
    asm volatile("mma.sync.aligned.m16n8k16.row.col.f32.f16.f16.f32 "
        "{%0,%1,%2,%3},{%4,%5,%6,%7},{%8,%9},{%0,%1,%2,%3};"
        : "+f"(d[0]), "+f"(d[1]), "+f"(d[2]), "+f"(d[3])
        : "r"(a[0]), "r"(a[1]), "r"(a[2]), "r"(a[3]), "r"(b0), "r"(b1));
}
__device__ __forceinline__ uint32_t smem_u32(const void* p) {
    uint32_t a;
    asm("{ .reg .u64 t; cvta.to.shared.u64 t, %1; cvt.u32.u64 %0, t; }" : "=r"(a) : "l"(p));
    return a;
}
#define CP_COMMIT() asm volatile("cp.async.commit_group;" ::: "memory")
#define CP_WAIT0()  asm volatile("cp.async.wait_group 0;" ::: "memory")

__global__ void k_prep(const float* __restrict__ w1, const float* __restrict__ w2,
                       const float* __restrict__ w3,
                       const float* __restrict__ wr1, const float* __restrict__ wr2,
                       const float* __restrict__ wf1, const float* __restrict__ wf2,
                       float* __restrict__ wt, uint2* __restrict__ wp) {
    int t0 = blockIdx.x * blockDim.x + threadIdx.x;
    int stride = gridDim.x * blockDim.x;
    for (int i = t0; i < 8192; i += stride)  { int c = i >> 7, o = i & 127; wt[i]         = wr1[o*64 + c]; }
    for (int i = t0; i < 16384; i += stride) { int c = i >> 7, o = i & 127; wt[8192 + i]  = wr2[o*128 + c]; }
    for (int i = t0; i < 32768; i += stride) { int c = i >> 8, o = i & 255; wt[24576 + i] = wf1[o*128 + c]; }
    for (int i = t0; i < 65536; i += stride) { int c = i >> 8, o = i & 255; wt[57344 + i] = wf2[o*256 + c]; }
    for (int i = t0; i < 6656; i += stride) {
        int lane = i & 31, rest = i >> 5;
        int o = rest & 7; rest >>= 3;
        int ks = rest % 13, cc = rest / 13;
        int gg = lane >> 2, tt = lane & 3;
        int oc = o*8 + gg, ic0 = cc*8 + 2*tt;
        int tap0 = 2*ks, tap1 = 2*ks + 1;
        uint2 pv;
        pv.x = f2h2(w1[oc*400 + ic0*25 + tap0], w1[oc*400 + (ic0+1)*25 + tap0]);
        pv.y = (tap1 < 25) ? f2h2(w1[oc*400 + ic0*25 + tap1], w1[oc*400 + (ic0+1)*25 + tap1]) : 0u;
        wp[i] = pv;
    }
    for (int i = t0; i < 9216; i += stride) {
        int lane = i & 31, rest = i >> 5;
        int o = rest & 7; rest >>= 3;
        int ks = rest % 9, cc = rest / 9;
        int gg = lane >> 2, tt = lane & 3;
        int oc = o*8 + gg;
        int icA = cc*16 + 2*tt, icB = cc*16 + 2*tt + 8;
        uint2 pv, qv;
        pv.x = f2h2(w2[oc*576 + icA*9 + ks], w2[oc*576 + (icA+1)*9 + ks]);
        pv.y = f2h2(w2[oc*576 + icB*9 + ks], w2[oc*576 + (icB+1)*9 + ks]);
        wp[6656 + i] = pv;
        qv.x = f2h2(w3[oc*576 + icA*9 + ks], w3[oc*576 + (icA+1)*9 + ks]);
        qv.y = f2h2(w3[oc*576 + icB*9 + ks], w3[oc*576 + (icB+1)*9 + ks]);
        wp[15872 + i] = qv;
    }
}

__global__ void k_build(const int* __restrict__ pos, const float* __restrict__ rt,
                        const float* __restrict__ emb, unsigned* __restrict__ X0h) {
    int n = blockIdx.y, q = blockIdx.x, t = threadIdx.x;
    __shared__ int s_px[RROOM], s_py[RROOM];
    __shared__ float s_emb[RROOM*EMBD];
    if (t < RROOM) { s_px[t] = pos[(n*RROOM+t)*2]; s_py[t] = pos[(n*RROOM+t)*2+1]; }
    if (t < RROOM*EMBD) s_emb[t] = emb[t];
    __syncthreads();
    int p0 = q * 1296, p1 = p0 + 1296;
    for (int pix = p0 + t; pix < p1; pix += blockDim.x) {
        int i = pix / MXY, j = pix % MXY;
        float acc[9], em[EMBD];
        #pragma unroll
        for (int c = 0; c < 9; c++) acc[c] = 0.f;
        #pragma unroll
        for (int e = 0; e < EMBD; e++) em[e] = 0.f;
        #pragma unroll 1
        for (int r = 0; r < RROOM; r++) {
            int w = i - s_px[r], h = j - s_py[r];
            if ((unsigned)w < (unsigned)WW && (unsigned)h < (unsigned)HH) {
                const float* rp = rt + (r*9)*(WW*HH) + w*HH + h;
                float m0 = rp[0];
                #pragma unroll
                for (int c = 0; c < 9; c++) acc[c] += rp[c*(WW*HH)];
                #pragma unroll
                for (int e = 0; e < EMBD; e++) em[e] += s_emb[r*EMBD+e] * m0;
            }
        }
        unsigned* xp = X0h + (size_t)n*8*PIX + pix;
        xp[0*PIX] = f2h2(acc[0], acc[1]);
        xp[1*PIX] = f2h2(acc[2], acc[3]);
        xp[2*PIX] = f2h2(acc[4], acc[5]);
        xp[3*PIX] = f2h2(acc[6], acc[7]);
        xp[4*PIX] = f2h2(acc[8], 1.0f);
        xp[5*PIX] = f2h2(em[0], em[1]);
        xp[6*PIX] = f2h2(em[2], em[3]);
        xp[7*PIX] = f2h2(em[4], em[5]);
    }
}

// conv5 16->64, ReLU. Mt=3; epilogue stores NHWC (for window gathers).
#define C5_A 53248
#define C5_TOT 82432
__global__ __launch_bounds__(384, 1)
void k_conv5_v2(const unsigned* __restrict__ in, const uint2* __restrict__ wp,
                const float* __restrict__ bias, unsigned* __restrict__ out) {
    extern __shared__ __align__(16) char smem[];
    uint32_t sb = smem_u32(smem);
    int t = threadIdx.x, warp = t >> 5, lane = t & 31;
    int g = lane >> 2, tig = lane & 3;
    int n = blockIdx.y, r0 = blockIdx.x * 8;
    const uint2* swf = (const uint2*)smem;
    const unsigned* sx = (const unsigned*)(smem + C5_A);
    const unsigned* inb = in + (size_t)n * 8 * PIX;

    float acc[3][8][4];
    #pragma unroll
    for (int a = 0; a < 3; a++)
        #pragma unroll
        for (int o = 0; o < 8; o++)
            #pragma unroll
            for (int k = 0; k < 4; k++) acc[a][o][k] = 0.f;

    unsigned axoff[3][2];
    #pragma unroll
    for (int t4 = 0; t4 < 3; t4++)
        #pragma unroll
        for (int gi = 0; gi < 2; gi++) {
            int p = warp*48 + t4*16 + g + gi*8;
            axoff[t4][gi] = (p/72)*76 + (p%72);
        }

    #pragma unroll
    for (int jj = 0; jj < 9; jj++) {
        int i = t + jj*384;
        if (i < 3328) {
            unsigned dst = sb + (unsigned)i*16u;
            const char* src = (const char*)wp + (size_t)i*16;
            asm volatile("cp.async.cg.shared.global [%0], [%1], 16;" :: "r"(dst), "l"(src) : "memory");
        }
    }
    #pragma unroll
    for (int jj = 0; jj < 19; jj++) {
        int i = t + jj*384;
        if (i < 7296) {
            int pair = i / 912; int s = i - pair*912;
            int rr = s / 76; int cx = s - rr*76;
            int gr = r0 - 2 + rr, gc = cx - 2;
            unsigned v = ((unsigned)gr < 72u && (unsigned)gc < 72u) ? 4u : 0u;
            const unsigned* gp = inb + (size_t)pair*PIX + (v ? (gr*72 + gc) : 0);
            unsigned dst = sb + C5_A + (unsigned)i*4u;
            asm volatile("cp.async.ca.shared.global [%0], [%1], 4, %2;"
                         :: "r"(dst), "l"(gp), "r"(v) : "memory");
        }
    }
    CP_COMMIT();
    CP_WAIT0();
    __syncthreads();

    #pragma unroll 1
    for (int cc = 0; cc < 2; cc++) {
        const unsigned* sxc = sx + (cc*4 + tig)*912;
        const uint2* wfc = swf + cc*3328;
        #pragma unroll
        for (int ks = 0; ks < 13; ks++) {
            const int tap0 = 2*ks;
            const int tap1 = (2*ks + 1 < 25) ? (2*ks + 1) : 24;
            const int off0 = (tap0/5)*76 + (tap0%5);
            const int off1 = (tap1/5)*76 + (tap1%5);
            unsigned av[3][4];
            #pragma unroll
            for (int t4 = 0; t4 < 3; t4++)
                #pragma unroll
                for (int gi = 0; gi < 2; gi++) {
                    av[t4][gi]     = sxc[axoff[t4][gi] + off0];
                    av[t4][2 + gi] = sxc[axoff[t4][gi] + off1];
                }
            #pragma unroll
            for (int o = 0; o < 8; o++) {
                uint2 b = wfc[ks*256 + o*32 + lane];
                mma_f16(acc[0][o], av[0], b.x, b.y);
                mma_f16(acc[1][o], av[1], b.x, b.y);
                mma_f16(acc[2][o], av[2], b.x, b.y);
            }
        }
    }

    unsigned* outb = out + (size_t)n * 32 * PIX;
    #pragma unroll
    for (int o = 0; o < 8; o++) {
        int oc0 = o*8 + 2*tig;
        float bv0 = bias[oc0], bv1 = bias[oc0 + 1];
        #pragma unroll
        for (int t4 = 0; t4 < 3; t4++)
            #pragma unroll
            for (int gi = 0; gi < 2; gi++) {
                int p = warp*48 + t4*16 + g + gi*8;
                int gr = r0 + p/72, gc = p%72;
                float v0 = fmaxf(acc[t4][o][gi*2 + 0] + bv0, 0.f);
                float v1 = fmaxf(acc[t4][o][gi*2 + 1] + bv1, 0.f);
                outb[(size_t)(gr*72 + gc)*32 + o*4 + tig] = f2h2(v0, v1);
            }
    }
}

// ---------------------------------------------------------------------------
// Layer 2 conv3, windowed. 12x10 input gather per room; 96-px padded output
// tiles; compact output [n][room][80px][32pair]. Out-of-image halo pixels
// stored as ZERO (layer-3 padding semantics).
// smem: weights @0 (73728), buf0/buf1 = 4 rooms x 12 rows x 360 words = 69120B.
// ---------------------------------------------------------------------------
#define W2_B0 73728
#define W2_B1 142848
#define W2_TOT 211968
__global__ __launch_bounds__(384, 1)
void k_conv3_win(const unsigned* __restrict__ xa, const uint2* __restrict__ wp,
                 const float* __restrict__ bias, const int* __restrict__ pos,
                 unsigned* __restrict__ xbw) {
    extern __shared__ __align__(16) char smem[];
    __shared__ int s_pos[16][2];
    uint32_t sb = smem_u32(smem);
    int t = threadIdx.x, warp = t >> 5, lane = t & 31;
    int g = lane >> 2, tig = lane & 3;
    int bx = blockIdx.x, n = bx >> 1, rbase = (bx & 1) * 16;
    const uint2* swf = (const uint2*)smem;
    const unsigned* xan = xa + (size_t)n * 32 * PIX;

    if (t < 32) s_pos[t >> 1][t & 1] = pos[(n*RROOM + rbase + (t >> 1))*2 + (t & 1)];

    // gather: 4 rooms x 12 rows x 10 cols x 8 quads = 3840 units (10 iters)
    #define W2_GATHER(ch, abase) do { \
        _Pragma("unroll") \
        for (int jj = 0; jj < 10; jj++) { \
            int i = t + jj*384; \
            int rr = i / 960; int rem = i - rr*960; \
            int wr2 = rem / 80; int u = rem - wr2*80; \
            int pc = u >> 3, q = u & 7; \
            int gr = s_pos[(ch)*4 + rr][0] - 2 + wr2; \
            int gc = s_pos[(ch)*4 + rr][1] - 2 + pc; \
            unsigned v = ((unsigned)gr < 72u && (unsigned)gc < 72u) ? 16u : 0u; \
            const unsigned* gp = xan + (v ? ((size_t)(gr*72 + gc)*32 + q*4) : 0); \
            unsigned dst = (abase) + (unsigned)(rr*4320 + wr2*360 + pc*36 + q*4)*4u; \
            asm volatile("cp.async.cg.shared.global [%0], [%1], 16, %2;" \
                         :: "r"(dst), "l"(gp), "r"(v) : "memory"); \
        } } while (0)

    // weights (73728B = 4608 x 16B)
    #pragma unroll
    for (int jj = 0; jj < 12; jj++) {
        int i = t + jj*384;
        unsigned dst = sb + (unsigned)i*16u;
        const char* src = (const char*)wp + (size_t)i*16;
        asm volatile("cp.async.cg.shared.global [%0], [%1], 16;" :: "r"(dst), "l"(src) : "memory");
    }
    __syncthreads();   // s_pos visible before gather
    W2_GATHER(0, sb + W2_B0);
    CP_COMMIT();
    CP_WAIT0();
    __syncthreads();

    int rw = warp / 3, wr = warp % 3;   // room-in-chunk, warp-in-room
    int pp[2][2];
    unsigned aw[2][2];
    #pragma unroll
    for (int t2 = 0; t2 < 2; t2++)
        #pragma unroll
        for (int gi = 0; gi < 2; gi++) {
            int p = (wr*2 + t2)*16 + g + gi*8;    // 0..95
            pp[t2][gi] = p;
            int pc96 = p < 80 ? p : 79;
            int xw = pc96 >> 3, yh = pc96 & 7;
            aw[t2][gi] = (unsigned)(rw*4320 + xw*360 + yh*36 + tig);
        }

    float bse[8], bso[8];
    #pragma unroll
    for (int o = 0; o < 8; o++) { bse[o] = bias[o*8 + 2*tig]; bso[o] = bias[o*8 + 2*tig + 1]; }

    #pragma unroll 1
    for (int ch = 0; ch < 4; ch++) {
        if (ch < 3) {
            W2_GATHER(ch+1, (ch & 1) ? (sb + W2_B0) : (sb + W2_B1));
            CP_COMMIT();
        }
        const unsigned* sx = (const unsigned*)(smem + ((ch & 1) ? W2_B1 : W2_B0));
        float acc[2][8][4];
        #pragma unroll
        for (int a = 0; a < 2; a++)
            #pragma unroll
            for (int o = 0; o < 8; o++)
                #pragma unroll
                for (int k = 0; k < 4; k++) acc[a][o][k] = 0.f;

        #pragma unroll 1
        for (int cc = 0; cc < 4; cc++) {
            const uint2* wfc = swf + cc*2304;
            #pragma unroll
            for (int ks = 0; ks < 9; ks++) {
                const int off = (ks/3)*360 + (ks%3)*36 + cc*8;
                unsigned av[2][4];
                #pragma unroll
                for (int t2 = 0; t2 < 2; t2++)
                    #pragma unroll
                    for (int gi = 0; gi < 2; gi++) {
                        av[t2][gi]     = sx[aw[t2][gi] + off];
                        av[t2][2 + gi] = sx[aw[t2][gi] + off + 4];
                    }
                #pragma unroll
                for (int o = 0; o < 8; o++) {
                    uint2 b = wfc[ks*256 + o*32 + lane];
                    mma_f16(acc[0][o], av[0], b.x, b.y);
                    mma_f16(acc[1][o], av[1], b.x, b.y);
                }
            }
        }

        // store compact window: [n][room][p][32pair], bias+ReLU.
        // out-of-image halo pixels -> ZERO (layer-3 zero-padding semantics)
        int prw = s_pos[ch*4 + rw][0], pcl = s_pos[ch*4 + rw][1];
        unsigned* ob = xbw + ((size_t)(n*RROOM + rbase + ch*4 + rw))*80*32;
        #pragma unroll
        for (int t2 = 0; t2 < 2; t2++)
            #pragma unroll
            for (int gi = 0; gi < 2; gi++) {
                int p = pp[t2][gi];
                if (p < 80) {
                    int gr = prw - 1 + (p >> 3);
                    int gc = pcl - 1 + (p & 7);
                    bool vld = ((unsigned)gr < 72u) && ((unsigned)gc < 72u);
                    #pragma unroll
                    for (int o = 0; o < 8; o++) {
                        float v0 = vld ? fmaxf(acc[t2][o][gi*2 + 0] + bse[o], 0.f) : 0.f;
                        float v1 = vld ? fmaxf(acc[t2][o][gi*2 + 1] + bso[o], 0.f) : 0.f;
                        ob[(size_t)p*32 + o*4 + tig] = f2h2(v0, v1);
                    }
                }
            }
        if (ch < 3) CP_WAIT0();
        __syncthreads();
    }
    #undef W2_GATHER
}

// ---------------------------------------------------------------------------
// Layer 3 conv3 + feat, fused. Input: compact windows (contiguous copy).
// ---------------------------------------------------------------------------
#define FW_B0 73728
#define FW_B1 119808
#define FW_TOT 165888
__global__ __launch_bounds__(384, 1)
void k_conv3_feat(const unsigned* __restrict__ xbw, const uint2* __restrict__ wp,
                  const float* __restrict__ bias, const float* __restrict__ rt,
                  float* __restrict__ feat) {
    extern __shared__ __align__(16) char smem[];
    __shared__ float s_feat[4][64];
    __shared__ float s_wm[16][48];
    __shared__ float s_rsum[16];
    uint32_t sb = smem_u32(smem);
    int t = threadIdx.x, warp = t >> 5, lane = t & 31;
    int g = lane >> 2, tig = lane & 3;
    int bx = blockIdx.x, n = bx >> 1, rbase = (bx & 1) * 16;
    const uint2* swf = (const uint2*)smem;

    for (int i = t; i < 16*48; i += 384) {
        int rr = i / 48, k = i % 48;
        s_wm[rr][k] = rt[(rbase + rr)*432 + k];
    }
    if (t < 256) s_feat[t >> 6][t & 63] = 0.f;
    __syncthreads();
    if (t < 16) {
        float s = 0.f;
        #pragma unroll
        for (int k = 0; k < 48; k++) s += s_wm[t][k];
        s_rsum[t] = s;
    }

    // contiguous copy: 4 rooms x 80 px x 8 quads = 2560 units
    #define FW_COPY(ch, abase) do { \
        const unsigned* srcb = xbw + ((size_t)(n*RROOM + rbase + (ch)*4))*80*32; \
        _Pragma("unroll") \
        for (int jj = 0; jj < 7; jj++) { \
            int i = t + jj*384; \
            if (i < 2560) { \
                int rr = i / 640; int rem = i - rr*640; \
                int px = rem >> 3, q = rem & 7; \
                const unsigned* gp = srcb + (size_t)(rr*80 + px)*32 + q*4; \
                unsigned dst = (abase) + (unsigned)(rr*2880 + px*36 + q*4)*4u; \
                asm volatile("cp.async.cg.shared.global [%0], [%1], 16;" \
                             :: "r"(dst), "l"(gp) : "memory"); \
            } \
        } } while (0)

    #pragma unroll
    for (int jj = 0; jj < 12; jj++) {
        int i = t + jj*384;
        unsigned dst = sb + (unsigned)i*16u;
        const char* src = (const char*)wp + (size_t)i*16;
        asm volatile("cp.async.cg.shared.global [%0], [%1], 16;" :: "r"(dst), "l"(src) : "memory");
    }
    FW_COPY(0, sb + FW_B0);
    CP_COMMIT();
    CP_WAIT0();
    __syncthreads();

    int rw = warp & 3, mt = warp >> 2;
    int p0 = mt*16 + g, p1 = p0 + 8;          // window pixels 0..47
    unsigned aw0 = (unsigned)(rw*2880 + (p0/6)*288 + (p0%6)*36 + tig);
    unsigned aw1 = (unsigned)(rw*2880 + (p1/6)*288 + (p1%6)*36 + tig);
    float bse[8], bso[8];
    #pragma unroll
    for (int o = 0; o < 8; o++) { bse[o] = bias[o*8 + 2*tig]; bso[o] = bias[o*8 + 2*tig + 1]; }

    #pragma unroll 1
    for (int ch = 0; ch < 4; ch++) {
        if (ch < 3) {
            FW_COPY(ch+1, (ch & 1) ? (sb + FW_B0) : (sb + FW_B1));
            CP_COMMIT();
        }
        const unsigned* sx = (const unsigned*)(smem + ((ch & 1) ? FW_B1 : FW_B0));
        float acc[8][4];
        #pragma unroll
        for (int o = 0; o < 8; o++)
            #pragma unroll
            for (int k = 0; k < 4; k++) acc[o][k] = 0.f;

        #pragma unroll 1
        for (int cc = 0; cc < 4; cc++) {
            const uint2* wfc = swf + cc*2304;
            #pragma unroll
            for (int ks = 0; ks < 9; ks++) {
                const int off = (ks/3)*288 + (ks%3)*36;
                unsigned av[4];
                av[0] = sx[aw0 + off + cc*8];
                av[1] = sx[aw1 + off + cc*8];
                av[2] = sx[aw0 + off + cc*8 + 4];
                av[3] = sx[aw1 + off + cc*8 + 4];
                #pragma unroll
                for (int o = 0; o < 8; o++) {
                    uint2 b = wfc[ks*256 + o*32 + lane];
                    mma_f16(acc[o], av, b.x, b.y);
                }
            }
        }

        float wm0 = s_wm[ch*4 + rw][p0];
        float wm1 = s_wm[ch*4 + rw][p1];
        #pragma unroll
        for (int o = 0; o < 8; o++) {
            float e = fmaxf(acc[o][0] + bse[o], 0.f)*wm0 + fmaxf(acc[o][2] + bse[o], 0.f)*wm1;
            float d2 = fmaxf(acc[o][1] + bso[o], 0.f)*wm0 + fmaxf(acc[o][3] + bso[o], 0.f)*wm1;
            e += __shfl_xor_sync(0xffffffffu, e, 16);
            e += __shfl_xor_sync(0xffffffffu, e, 8);
            e += __shfl_xor_sync(0xffffffffu, e, 4);
            d2 += __shfl_xor_sync(0xffffffffu, d2, 16);
            d2 += __shfl_xor_sync(0xffffffffu, d2, 8);
            d2 += __shfl_xor_sync(0xffffffffu, d2, 4);
            if (g == 0) {
                atomicAdd(&s_feat[rw][o*8 + 2*tig], e);
                atomicAdd(&s_feat[rw][o*8 + 2*tig + 1], d2);
            }
        }
        __syncthreads();
        if (t < 256) {
            int rr = t >> 6, oc = t & 63;
            feat[(n*RROOM + rbase + ch*4 + rr)*64 + oc] = s_feat[rr][oc] / s_rsum[ch*4 + rr];
            s_feat[rr][oc] = 0.f;
        }
        if (ch < 3) CP_WAIT0();
        __syncthreads();
    }
    #undef FW_COPY
}

__global__ __launch_bounds__(128)
void k_room(const float* __restrict__ feat, const float* __restrict__ wt,
            const float* __restrict__ b1, const float* __restrict__ b2,
            float* __restrict__ S) {
    const float* w1t = wt;
    const float* w2t = wt + 8192;
    int n = blockIdx.x, o = threadIdx.x;
    __shared__ float s_f[4][64];
    __shared__ float s_h1[4][128];
    float accS = 0.f;
    float bb1 = b1[o], bb2 = b2[o];
    for (int rg = 0; rg < 8; rg++) {
        #pragma unroll
        for (int i = o; i < 256; i += 128) {
            int r = i >> 6, c = i & 63;
            s_f[r][c] = feat[(n*RROOM + rg*4 + r)*64 + c];
        }
        __syncthreads();
        float a0 = bb1, a1 = bb1, a2 = bb1, a3 = bb1;
        #pragma unroll
        for (int c = 0; c < 64; c++) {
            float wv = w1t[c*128 + o];
            a0 += wv * s_f[0][c]; a1 += wv * s_f[1][c];
            a2 += wv * s_f[2][c]; a3 += wv * s_f[3][c];
        }
        s_h1[0][o] = fmaxf(a0, 0.f); s_h1[1][o] = fmaxf(a1, 0.f);
        s_h1[2][o] = fmaxf(a2, 0.f); s_h1[3][o] = fmaxf(a3, 0.f);
        __syncthreads();
        float z0 = bb2, z1 = bb2, z2 = bb2, z3 = bb2;
        #pragma unroll
        for (int c = 0; c < 128; c++) {
            float wv = w2t[c*128 + o];
            z0 += wv * s_h1[0][c]; z1 += wv * s_h1[1][c];
            z2 += wv * s_h1[2][c]; z3 += wv * s_h1[3][c];
        }
        accS += fmaxf(z0, 0.f) + fmaxf(z1, 0.f) + fmaxf(z2, 0.f) + fmaxf(z3, 0.f);
        __syncthreads();
    }
    S[n*128 + o] = accS;
}

__global__ __launch_bounds__(256)
void k_fc(const float* __restrict__ S, const float* __restrict__ wt,
          const float* __restrict__ bf1, const float* __restrict__ bf2,
          float* __restrict__ out) {
    const float* wf1t = wt + 24576;
    const float* wf2t = wt + 57344;
    int n0 = blockIdx.x * 4, o = threadIdx.x;
    __shared__ float s_in[4][128];
    __shared__ float s_h[4][256];
    #pragma unroll
    for (int i = o; i < 512; i += 256) {
        int q = i >> 7, c = i & 127;
        s_in[q][c] = S[(n0 + q)*128 + c];
    }
    __syncthreads();
    float a0 = bf1[o], a1 = a0, a2 = a0, a3 = a0;
    #pragma unroll
    for (int c = 0; c < 128; c++) {
        float wv = wf1t[c*256 + o];
        a0 += wv * s_in[0][c]; a1 += wv * s_in[1][c];
        a2 += wv * s_in[2][c]; a3 += wv * s_in[3][c];
    }
    s_h[0][o] = fmaxf(a0, 0.f); s_h[1][o] = fmaxf(a1, 0.f);
    s_h[2][o] = fmaxf(a2, 0.f); s_h[3][o] = fmaxf(a3, 0.f);
    __syncthreads();
    float z0 = bf2[o], z1 = z0, z2 = z0, z3 = z0;
    #pragma unroll
    for (int c = 0; c < 256; c++) {
        float wv = wf2t[c*256 + o];
        z0 += wv * s_h[0][c]; z1 += wv * s_h[1][c];
        z2 += wv * s_h[2][c]; z3 += wv * s_h[3][c];
    }
    out[(n0 + 0)*256 + o] = z0;
    out[(n0 + 1)*256 + o] = z1;
    out[(n0 + 2)*256 + o] = z2;
    out[(n0 + 3)*256 + o] = z3;
}

extern "C" void kernel_launch(void* const* d_in, const int* in_sizes, int n_in,
                              void* d_out, int out_size) {
    const int*   pos = (const int*)d_in[0];
    const float* rt  = (const float*)d_in[1];
    const float* emb = (const float*)d_in[2];
    const float* w1  = (const float*)d_in[3];
    const float* b1  = (const float*)d_in[4];
    const float* w2  = (const float*)d_in[5];
    const float* b2  = (const float*)d_in[6];
    const float* w3  = (const float*)d_in[7];
    const float* b3  = (const float*)d_in[8];
    const float* wr1 = (const float*)d_in[9];
    const float* br1 = (const float*)d_in[10];
    const float* wr2 = (const float*)d_in[11];
    const float* br2 = (const float*)d_in[12];
    const float* wf1 = (const float*)d_in[13];
    const float* bf1 = (const float*)d_in[14];
    const float* wf2 = (const float*)d_in[15];
    const float* bf2 = (const float*)d_in[16];
    float* out = (float*)d_out;

    unsigned *X0h, *XAh, *XBw;
    float *feat, *S, *wt;
    uint2 *wpk;
    cudaGetSymbolAddress((void**)&X0h, g_X0h);
    cudaGetSymbolAddress((void**)&XAh, g_XAh);
    cudaGetSymbolAddress((void**)&XBw, g_XBw);
    cudaGetSymbolAddress((void**)&feat, g_feat);
    cudaGetSymbolAddress((void**)&S, g_S);
    cudaGetSymbolAddress((void**)&wt, g_wt);
    cudaGetSymbolAddress((void**)&wpk, g_wp);

    cudaFuncSetAttribute(k_conv5_v2, cudaFuncAttributeMaxDynamicSharedMemorySize, C5_TOT);
    cudaFuncSetAttribute(k_conv3_win, cudaFuncAttributeMaxDynamicSharedMemorySize, W2_TOT);
    cudaFuncSetAttribute(k_conv3_feat, cudaFuncAttributeMaxDynamicSharedMemorySize, FW_TOT);

    k_prep<<<96, 256>>>(w1, w2, w3, wr1, wr2, wf1, wf2, wt, wpk);
    k_build<<<dim3(4, NIMG), 256>>>(pos, rt, emb, X0h);
    k_conv5_v2<<<dim3(9, NIMG), 384, C5_TOT>>>(X0h, wpk, b1, XAh);
    k_conv3_win<<<NIMG*2, 384, W2_TOT>>>(XAh, wpk + 6656, b2, pos, XBw);
    k_conv3_feat<<<NIMG*2, 384, FW_TOT>>>(XBw, wpk + 15872, b3, rt, feat);
    k_room<<<NIMG, 128>>>(feat, wt, br1, br2, S);
    k_fc<<<NIMG/4, 256>>>(S, wt, bf1, bf2, out);
}

// round 15
// speedup vs baseline: 1.3734x; 1.3734x over previous
#include <cuda_runtime.h>
#include <cuda_fp16.h>
#include <cstdint>

#define NIMG 256
#define RROOM 32
#define WW 8
#define HH 6
#define MXY 72
#define PIX (MXY*MXY)
#define EMBD 6

__device__ __align__(16) unsigned g_X0h[NIMG*8*PIX];
__device__ __align__(16) unsigned g_XAh[NIMG*32*PIX];   // conv5 out, NHWC (32 half2/px)
__device__ float g_feat[NIMG*RROOM*64];
__device__ float g_S[NIMG*128];
__device__ float g_wt[122880];
__device__ __align__(16) uint2 g_wp[25088];  // conv5 @0, conv3A @6656, conv3B @15872

__device__ __forceinline__ unsigned f2h2(float lo, float hi) {
    __half2 h = __floats2half2_rn(lo, hi);
    return *reinterpret_cast<unsigned*>(&h);
}
__device__ __forceinline__ void mma_f16(float d[4], const unsigned a[4], unsigned b0, unsigned b1) {
    asm volatile("mma.sync.aligned.m16n8k16.row.col.f32.f16.f16.f32 "
        "{%0,%1,%2,%3},{%4,%5,%6,%7},{%8,%9},{%0,%1,%2,%3};"
        : "+f"(d[0]), "+f"(d[1]), "+f"(d[2]), "+f"(d[3])
        : "r"(a[0]), "r"(a[1]), "r"(a[2]), "r"(a[3]), "r"(b0), "r"(b1));
}
__device__ __forceinline__ uint32_t smem_u32(const void* p) {
    uint32_t a;
    asm("{ .reg .u64 t; cvta.to.shared.u64 t, %1; cvt.u32.u64 %0, t; }" : "=r"(a) : "l"(p));
    return a;
}
#define CP_COMMIT() asm volatile("cp.async.commit_group;" ::: "memory")
#define CP_WAIT0()  asm volatile("cp.async.wait_group 0;" ::: "memory")

__global__ void k_prep(const float* __restrict__ w1, const float* __restrict__ w2,
                       const float* __restrict__ w3,
                       const float* __restrict__ wr1, const float* __restrict__ wr2,
                       const float* __restrict__ wf1, const float* __restrict__ wf2,
                       float* __restrict__ wt, uint2* __restrict__ wp) {
    int t0 = blockIdx.x * blockDim.x + threadIdx.x;
    int stride = gridDim.x * blockDim.x;
    for (int i = t0; i < 8192; i += stride)  { int c = i >> 7, o = i & 127; wt[i]         = wr1[o*64 + c]; }
    for (int i = t0; i < 16384; i += stride) { int c = i >> 7, o = i & 127; wt[8192 + i]  = wr2[o*128 + c]; }
    for (int i = t0; i < 32768; i += stride) { int c = i >> 8, o = i & 255; wt[24576 + i] = wf1[o*128 + c]; }
    for (int i = t0; i < 65536; i += stride) { int c = i >> 8, o = i & 255; wt[57344 + i] = wf2[o*256 + c]; }
    for (int i = t0; i < 6656; i += stride) {
        int lane = i & 31, rest = i >> 5;
        int o = rest & 7; rest >>= 3;
        int ks = rest % 13, cc = rest / 13;
        int gg = lane >> 2, tt = lane & 3;
        int oc = o*8 + gg, ic0 = cc*8 + 2*tt;
        int tap0 = 2*ks, tap1 = 2*ks + 1;
        uint2 pv;
        pv.x = f2h2(w1[oc*400 + ic0*25 + tap0], w1[oc*400 + (ic0+1)*25 + tap0]);
        pv.y = (tap1 < 25) ? f2h2(w1[oc*400 + ic0*25 + tap1], w1[oc*400 + (ic0+1)*25 + tap1]) : 0u;
        wp[i] = pv;
    }
    for (int i = t0; i < 9216; i += stride) {
        int lane = i & 31, rest = i >> 5;
        int o = rest & 7; rest >>= 3;
        int ks = rest % 9, cc = rest / 9;
        int gg = lane >> 2, tt = lane & 3;
        int oc = o*8 + gg;
        int icA = cc*16 + 2*tt, icB = cc*16 + 2*tt + 8;
        uint2 pv, qv;
        pv.x = f2h2(w2[oc*576 + icA*9 + ks], w2[oc*576 + (icA+1)*9 + ks]);
        pv.y = f2h2(w2[oc*576 + icB*9 + ks], w2[oc*576 + (icB+1)*9 + ks]);
        wp[6656 + i] = pv;
        qv.x = f2h2(w3[oc*576 + icA*9 + ks], w3[oc*576 + (icA+1)*9 + ks]);
        qv.y = f2h2(w3[oc*576 + icB*9 + ks], w3[oc*576 + (icB+1)*9 + ks]);
        wp[15872 + i] = qv;
    }
}

__global__ void k_build(const int* __restrict__ pos, const float* __restrict__ rt,
                        const float* __restrict__ emb, unsigned* __restrict__ X0h) {
    int n = blockIdx.y, q = blockIdx.x, t = threadIdx.x;
    __shared__ int s_px[RROOM], s_py[RROOM];
    __shared__ float s_emb[RROOM*EMBD];
    if (t < RROOM) { s_px[t] = pos[(n*RROOM+t)*2]; s_py[t] = pos[(n*RROOM+t)*2+1]; }
    if (t < RROOM*EMBD) s_emb[t] = emb[t];
    __syncthreads();
    int p0 = q * 1296, p1 = p0 + 1296;
    for (int pix = p0 + t; pix < p1; pix += blockDim.x) {
        int i = pix / MXY, j = pix % MXY;
        float acc[9], em[EMBD];
        #pragma unroll
        for (int c = 0; c < 9; c++) acc[c] = 0.f;
        #pragma unroll
        for (int e = 0; e < EMBD; e++) em[e] = 0.f;
        #pragma unroll 1
        for (int r = 0; r < RROOM; r++) {
            int w = i - s_px[r], h = j - s_py[r];
            if ((unsigned)w < (unsigned)WW && (unsigned)h < (unsigned)HH) {
                const float* rp = rt + (r*9)*(WW*HH) + w*HH + h;
                float m0 = rp[0];
                #pragma unroll
                for (int c = 0; c < 9; c++) acc[c] += rp[c*(WW*HH)];
                #pragma unroll
                for (int e = 0; e < EMBD; e++) em[e] += s_emb[r*EMBD+e] * m0;
            }
        }
        unsigned* xp = X0h + (size_t)n*8*PIX + pix;
        xp[0*PIX] = f2h2(acc[0], acc[1]);
        xp[1*PIX] = f2h2(acc[2], acc[3]);
        xp[2*PIX] = f2h2(acc[4], acc[5]);
        xp[3*PIX] = f2h2(acc[6], acc[7]);
        xp[4*PIX] = f2h2(acc[8], 1.0f);
        xp[5*PIX] = f2h2(em[0], em[1]);
        xp[6*PIX] = f2h2(em[2], em[3]);
        xp[7*PIX] = f2h2(em[4], em[5]);
    }
}

// conv5 16->64, ReLU, NHWC out. Epilogue staged through smem for coalesced STG.
#define C5_A 53248
#define C5_TOT 82944
__global__ __launch_bounds__(384, 1)
void k_conv5_v3(const unsigned* __restrict__ in, const uint2* __restrict__ wp,
                const float* __restrict__ bias, unsigned* __restrict__ out) {
    extern __shared__ __align__(16) char smem[];
    uint32_t sb = smem_u32(smem);
    int t = threadIdx.x, warp = t >> 5, lane = t & 31;
    int g = lane >> 2, tig = lane & 3;
    int n = blockIdx.y, r0 = blockIdx.x * 8;
    const uint2* swf = (const uint2*)smem;
    const unsigned* sx = (const unsigned*)(smem + C5_A);
    const unsigned* inb = in + (size_t)n * 8 * PIX;

    float acc[3][8][4];
    #pragma unroll
    for (int a = 0; a < 3; a++)
        #pragma unroll
        for (int o = 0; o < 8; o++)
            #pragma unroll
            for (int k = 0; k < 4; k++) acc[a][o][k] = 0.f;

    unsigned axoff[3][2];
    int ppix[3][2];
    #pragma unroll
    for (int t4 = 0; t4 < 3; t4++)
        #pragma unroll
        for (int gi = 0; gi < 2; gi++) {
            int p = warp*48 + t4*16 + g + gi*8;
            ppix[t4][gi] = p;
            axoff[t4][gi] = (p/72)*76 + (p%72);
        }

    #pragma unroll
    for (int jj = 0; jj < 9; jj++) {
        int i = t + jj*384;
        if (i < 3328) {
            unsigned dst = sb + (unsigned)i*16u;
            const char* src = (const char*)wp + (size_t)i*16;
            asm volatile("cp.async.cg.shared.global [%0], [%1], 16;" :: "r"(dst), "l"(src) : "memory");
        }
    }
    #pragma unroll
    for (int jj = 0; jj < 19; jj++) {
        int i = t + jj*384;
        if (i < 7296) {
            int pair = i / 912; int s = i - pair*912;
            int rr = s / 76; int cx = s - rr*76;
            int gr = r0 - 2 + rr, gc = cx - 2;
            unsigned v = ((unsigned)gr < 72u && (unsigned)gc < 72u) ? 4u : 0u;
            const unsigned* gp = inb + (size_t)pair*PIX + (v ? (gr*72 + gc) : 0);
            unsigned dst = sb + C5_A + (unsigned)i*4u;
            asm volatile("cp.async.ca.shared.global [%0], [%1], 4, %2;"
                         :: "r"(dst), "l"(gp), "r"(v) : "memory");
        }
    }
    CP_COMMIT();
    CP_WAIT0();
    __syncthreads();

    #pragma unroll 1
    for (int cc = 0; cc < 2; cc++) {
        const unsigned* sxc = sx + (cc*4 + tig)*912;
        const uint2* wfc = swf + cc*3328;
        #pragma unroll
        for (int ks = 0; ks < 13; ks++) {
            const int tap0 = 2*ks;
            const int tap1 = (2*ks + 1 < 25) ? (2*ks + 1) : 24;
            const int off0 = (tap0/5)*76 + (tap0%5);
            const int off1 = (tap1/5)*76 + (tap1%5);
            unsigned av[3][4];
            #pragma unroll
            for (int t4 = 0; t4 < 3; t4++)
                #pragma unroll
                for (int gi = 0; gi < 2; gi++) {
                    av[t4][gi]     = sxc[axoff[t4][gi] + off0];
                    av[t4][2 + gi] = sxc[axoff[t4][gi] + off1];
                }
            #pragma unroll
            for (int o = 0; o < 8; o++) {
                uint2 b = wfc[ks*256 + o*32 + lane];
                mma_f16(acc[0][o], av[0], b.x, b.y);
                mma_f16(acc[1][o], av[1], b.x, b.y);
                mma_f16(acc[2][o], av[2], b.x, b.y);
            }
        }
    }

    // staged NHWC epilogue: smem (36-word px stride) -> coalesced 16B STG
    __syncthreads();
    unsigned* stg = (unsigned*)smem;
    #pragma unroll
    for (int o = 0; o < 8; o++) {
        int oc0 = o*8 + 2*tig;
        float bv0 = bias[oc0], bv1 = bias[oc0 + 1];
        #pragma unroll
        for (int t4 = 0; t4 < 3; t4++)
            #pragma unroll
            for (int gi = 0; gi < 2; gi++) {
                int p = ppix[t4][gi];
                float v0 = fmaxf(acc[t4][o][gi*2 + 0] + bv0, 0.f);
                float v1 = fmaxf(acc[t4][o][gi*2 + 1] + bv1, 0.f);
                stg[p*36 + o*4 + tig] = f2h2(v0, v1);
            }
    }
    __syncthreads();
    unsigned* outb = out + (size_t)n * 32 * PIX;
    #pragma unroll
    for (int jj = 0; jj < 12; jj++) {
        int u = t + jj*384;          // 4608 = 576px x 8 quads
        int p = u >> 3, q = u & 7;
        int gr = r0 + p/72, gc = p%72;
        uint4 v = *(const uint4*)(stg + p*36 + q*4);
        *(uint4*)(outb + (size_t)(gr*72 + gc)*32 + q*4) = v;
    }
}

// ---------------------------------------------------------------------------
// FUSED layers 2+3 + feat, windowed, per (image, 16 rooms); 8 chunks x 2 rooms.
// L2: gather 12x10 XA windows -> conv3 -> window in SMEM (zero-masked).
// L3: conv3 on window + room-map pooling -> feat. No global intermediate.
// smem: W2 @0 (73728), W3 @73728 (73728), IN @147456 (34560), WIN @182016 (23040).
// ---------------------------------------------------------------------------
#define F_W3 73728
#define F_IN 147456
#define F_WIN 182016
#define F_TOT 205056
__global__ __launch_bounds__(384, 1)
void k_winfused(const unsigned* __restrict__ xa, const uint2* __restrict__ wp2,
                const uint2* __restrict__ wp3,
                const float* __restrict__ bias2, const float* __restrict__ bias3,
                const float* __restrict__ rt, const int* __restrict__ pos,
                float* __restrict__ feat) {
    extern __shared__ __align__(16) char smem[];
    __shared__ float s_feat[2][64];
    __shared__ float s_wm[16][48];
    __shared__ float s_rsum[16];
    __shared__ int s_pos[16][2];
    uint32_t sb = smem_u32(smem);
    int t = threadIdx.x, warp = t >> 5, lane = t & 31;
    int g = lane >> 2, tig = lane & 3;
    int bx = blockIdx.x, n = bx >> 1, rbase = (bx & 1) * 16;
    const uint2* swf2 = (const uint2*)smem;
    const uint2* swf3 = (const uint2*)(smem + F_W3);
    const unsigned* INs = (const unsigned*)(smem + F_IN);
    unsigned* WINs = (unsigned*)(smem + F_WIN);
    const unsigned* xan = xa + (size_t)n * 32 * PIX;

    for (int i = t; i < 16*48; i += 384) {
        int rr = i / 48, k = i % 48;
        s_wm[rr][k] = rt[(rbase + rr)*432 + k];
    }
    if (t < 32) s_pos[t >> 1][t & 1] = pos[(n*RROOM + rbase + (t >> 1))*2 + (t & 1)];
    if (t < 128) s_feat[t >> 6][t & 63] = 0.f;

    // both weight sets: 9216 x 16B
    #pragma unroll
    for (int jj = 0; jj < 12; jj++) {
        int i = t + jj*384;
        asm volatile("cp.async.cg.shared.global [%0], [%1], 16;"
                     :: "r"(sb + (unsigned)i*16u), "l"((const char*)wp2 + (size_t)i*16) : "memory");
    }
    #pragma unroll
    for (int jj = 0; jj < 12; jj++) {
        int i = t + jj*384;
        asm volatile("cp.async.cg.shared.global [%0], [%1], 16;"
                     :: "r"(sb + F_W3 + (unsigned)i*16u), "l"((const char*)wp3 + (size_t)i*16) : "memory");
    }
    __syncthreads();
    if (t < 16) {
        float s = 0.f;
        #pragma unroll
        for (int k = 0; k < 48; k++) s += s_wm[t][k];
        s_rsum[t] = s;
    }

    // warp roles
    int rw2 = warp / 6, mt6 = warp % 6;              // L2: room, m16-tile of 96px
    int pp2[2];
    unsigned aw2[2];
    #pragma unroll
    for (int gi = 0; gi < 2; gi++) {
        int p = mt6*16 + g + gi*8;                   // 0..95
        pp2[gi] = p;
        int pc96 = p < 80 ? p : 79;
        aw2[gi] = (unsigned)(rw2*4320 + (pc96 >> 3)*360 + (pc96 & 7)*36 + tig);
    }
    int rw3 = warp / 6, sub3 = warp % 6;             // L3: room, (mt, oc-half)
    int mt3 = sub3 >> 1, half3 = sub3 & 1;
    int p0 = mt3*16 + g, p1 = p0 + 8;                // 0..47
    unsigned aw0 = (unsigned)(rw3*2880 + (p0/6)*288 + (p0%6)*36 + tig);
    unsigned aw1 = (unsigned)(rw3*2880 + (p1/6)*288 + (p1%6)*36 + tig);

    float bse2[8], bso2[8];
    #pragma unroll
    for (int o = 0; o < 8; o++) { bse2[o] = bias2[o*8 + 2*tig]; bso2[o] = bias2[o*8 + 2*tig + 1]; }
    float bse3[4], bso3[4];
    #pragma unroll
    for (int o = 0; o < 4; o++) {
        bse3[o] = bias3[(half3*4 + o)*8 + 2*tig];
        bso3[o] = bias3[(half3*4 + o)*8 + 2*tig + 1];
    }

    #pragma unroll 1
    for (int ch = 0; ch < 8; ch++) {
        // gather 2 rooms x 12x10 px x 8 quads = 1920 units
        #pragma unroll
        for (int jj = 0; jj < 5; jj++) {
            int i = t + jj*384;
            int rr = i / 960; int rem = i - rr*960;
            int wr2 = rem / 80; int u = rem - wr2*80;
            int pc = u >> 3, q = u & 7;
            int gr = s_pos[ch*2 + rr][0] - 2 + wr2;
            int gc = s_pos[ch*2 + rr][1] - 2 + pc;
            unsigned v = ((unsigned)gr < 72u && (unsigned)gc < 72u) ? 16u : 0u;
            const unsigned* gp = xan + (v ? ((size_t)(gr*72 + gc)*32 + q*4) : 0);
            unsigned dst = sb + F_IN + (unsigned)(rr*4320 + wr2*360 + pc*36 + q*4)*4u;
            asm volatile("cp.async.cg.shared.global [%0], [%1], 16, %2;"
                         :: "r"(dst), "l"(gp), "r"(v) : "memory");
        }
        CP_COMMIT();
        CP_WAIT0();
        __syncthreads();

        // ---- L2 conv3 ----
        float acc2[8][4];
        #pragma unroll
        for (int o = 0; o < 8; o++)
            #pragma unroll
            for (int k = 0; k < 4; k++) acc2[o][k] = 0.f;
        #pragma unroll 1
        for (int cc = 0; cc < 4; cc++) {
            const uint2* wfc = swf2 + cc*2304;
            #pragma unroll
            for (int ks = 0; ks < 9; ks++) {
                const int off = (ks/3)*360 + (ks%3)*36 + cc*8;
                unsigned av[4];
                av[0] = INs[aw2[0] + off];
                av[1] = INs[aw2[1] + off];
                av[2] = INs[aw2[0] + off + 4];
                av[3] = INs[aw2[1] + off + 4];
                #pragma unroll
                for (int o = 0; o < 8; o++) {
                    uint2 b = wfc[ks*256 + o*32 + lane];
                    mma_f16(acc2[o], av, b.x, b.y);
                }
            }
        }
        // window store (smem), zero for out-of-image pixels
        {
            int prw = s_pos[ch*2 + rw2][0], pcl = s_pos[ch*2 + rw2][1];
            #pragma unroll
            for (int gi = 0; gi < 2; gi++) {
                int p = pp2[gi];
                if (p < 80) {
                    int gr = prw - 1 + (p >> 3);
                    int gc = pcl - 1 + (p & 7);
                    bool vld = ((unsigned)gr < 72u) && ((unsigned)gc < 72u);
                    #pragma unroll
                    for (int o = 0; o < 8; o++) {
                        float v0 = vld ? fmaxf(acc2[o][gi*2 + 0] + bse2[o], 0.f) : 0.f;
                        float v1 = vld ? fmaxf(acc2[o][gi*2 + 1] + bso2[o], 0.f) : 0.f;
                        WINs[rw2*2880 + p*36 + o*4 + tig] = f2h2(v0, v1);
                    }
                }
            }
        }
        __syncthreads();

        // ---- L3 conv3 + pooled feat ----
        float acc3[4][4];
        #pragma unroll
        for (int o = 0; o < 4; o++)
            #pragma unroll
            for (int k = 0; k < 4; k++) acc3[o][k] = 0.f;
        #pragma unroll 1
        for (int cc = 0; cc < 4; cc++) {
            const uint2* wfc = swf3 + cc*2304;
            #pragma unroll
            for (int ks = 0; ks < 9; ks++) {
                const int off = (ks/3)*288 + (ks%3)*36 + cc*8;
                unsigned av[4];
                av[0] = WINs[aw0 + off];
                av[1] = WINs[aw1 + off];
                av[2] = WINs[aw0 + off + 4];
                av[3] = WINs[aw1 + off + 4];
                #pragma unroll
                for (int o = 0; o < 4; o++) {
                    uint2 b = wfc[ks*256 + (half3*4 + o)*32 + lane];
                    mma_f16(acc3[o], av, b.x, b.y);
                }
            }
        }
        float wm0 = s_wm[ch*2 + rw3][p0];
        float wm1 = s_wm[ch*2 + rw3][p1];
        #pragma unroll
        for (int o = 0; o < 4; o++) {
            float e = fmaxf(acc3[o][0] + bse3[o], 0.f)*wm0 + fmaxf(acc3[o][2] + bse3[o], 0.f)*wm1;
            float d2 = fmaxf(acc3[o][1] + bso3[o], 0.f)*wm0 + fmaxf(acc3[o][3] + bso3[o], 0.f)*wm1;
            e += __shfl_xor_sync(0xffffffffu, e, 16);
            e += __shfl_xor_sync(0xffffffffu, e, 8);
            e += __shfl_xor_sync(0xffffffffu, e, 4);
            d2 += __shfl_xor_sync(0xffffffffu, d2, 16);
            d2 += __shfl_xor_sync(0xffffffffu, d2, 8);
            d2 += __shfl_xor_sync(0xffffffffu, d2, 4);
            if (g == 0) {
                atomicAdd(&s_feat[rw3][(half3*4 + o)*8 + 2*tig], e);
                atomicAdd(&s_feat[rw3][(half3*4 + o)*8 + 2*tig + 1], d2);
            }
        }
        __syncthreads();
        if (t < 128) {
            int rr = t >> 6, oc = t & 63;
            feat[(n*RROOM + rbase + ch*2 + rr)*64 + oc] = s_feat[rr][oc] / s_rsum[ch*2 + rr];
            s_feat[rr][oc] = 0.f;
        }
        __syncthreads();
    }
}

__global__ __launch_bounds__(128)
void k_room(const float* __restrict__ feat, const float* __restrict__ wt,
            const float* __restrict__ b1, const float* __restrict__ b2,
            float* __restrict__ S) {
    const float* w1t = wt;
    const float* w2t = wt + 8192;
    int n = blockIdx.x, o = threadIdx.x;
    __shared__ float s_f[4][64];
    __shared__ float s_h1[4][128];
    float accS = 0.f;
    float bb1 = b1[o], bb2 = b2[o];
    for (int rg = 0; rg < 8; rg++) {
        #pragma unroll
        for (int i = o; i < 256; i += 128) {
            int r = i >> 6, c = i & 63;
            s_f[r][c] = feat[(n*RROOM + rg*4 + r)*64 + c];
        }
        __syncthreads();
        float a0 = bb1, a1 = bb1, a2 = bb1, a3 = bb1;
        #pragma unroll
        for (int c = 0; c < 64; c++) {
            float wv = w1t[c*128 + o];
            a0 += wv * s_f[0][c]; a1 += wv * s_f[1][c];
            a2 += wv * s_f[2][c]; a3 += wv * s_f[3][c];
        }
        s_h1[0][o] = fmaxf(a0, 0.f); s_h1[1][o] = fmaxf(a1, 0.f);
        s_h1[2][o] = fmaxf(a2, 0.f); s_h1[3][o] = fmaxf(a3, 0.f);
        __syncthreads();
        float z0 = bb2, z1 = bb2, z2 = bb2, z3 = bb2;
        #pragma unroll
        for (int c = 0; c < 128; c++) {
            float wv = w2t[c*128 + o];
            z0 += wv * s_h1[0][c]; z1 += wv * s_h1[1][c];
            z2 += wv * s_h1[2][c]; z3 += wv * s_h1[3][c];
        }
        accS += fmaxf(z0, 0.f) + fmaxf(z1, 0.f) + fmaxf(z2, 0.f) + fmaxf(z3, 0.f);
        __syncthreads();
    }
    S[n*128 + o] = accS;
}

__global__ __launch_bounds__(256)
void k_fc(const float* __restrict__ S, const float* __restrict__ wt,
          const float* __restrict__ bf1, const float* __restrict__ bf2,
          float* __restrict__ out) {
    const float* wf1t = wt + 24576;
    const float* wf2t = wt + 57344;
    int n0 = blockIdx.x * 4, o = threadIdx.x;
    __shared__ float s_in[4][128];
    __shared__ float s_h[4][256];
    #pragma unroll
    for (int i = o; i < 512; i += 256) {
        int q = i >> 7, c = i & 127;
        s_in[q][c] = S[(n0 + q)*128 + c];
    }
    __syncthreads();
    float a0 = bf1[o], a1 = a0, a2 = a0, a3 = a0;
    #pragma unroll
    for (int c = 0; c < 128; c++) {
        float wv = wf1t[c*256 + o];
        a0 += wv * s_in[0][c]; a1 += wv * s_in[1][c];
        a2 += wv * s_in[2][c]; a3 += wv * s_in[3][c];
    }
    s_h[0][o] = fmaxf(a0, 0.f); s_h[1][o] = fmaxf(a1, 0.f);
    s_h[2][o] = fmaxf(a2, 0.f); s_h[3][o] = fmaxf(a3, 0.f);
    __syncthreads();
    float z0 = bf2[o], z1 = z0, z2 = z0, z3 = z0;
    #pragma unroll
    for (int c = 0; c < 256; c++) {
        float wv = wf2t[c*256 + o];
        z0 += wv * s_h[0][c]; z1 += wv * s_h[1][c];
        z2 += wv * s_h[2][c]; z3 += wv * s_h[3][c];
    }
    out[(n0 + 0)*256 + o] = z0;
    out[(n0 + 1)*256 + o] = z1;
    out[(n0 + 2)*256 + o] = z2;
    out[(n0 + 3)*256 + o] = z3;
}

extern "C" void kernel_launch(void* const* d_in, const int* in_sizes, int n_in,
                              void* d_out, int out_size) {
    const int*   pos = (const int*)d_in[0];
    const float* rt  = (const float*)d_in[1];
    const float* emb = (const float*)d_in[2];
    const float* w1  = (const float*)d_in[3];
    const float* b1  = (const float*)d_in[4];
    const float* w2  = (const float*)d_in[5];
    const float* b2  = (const float*)d_in[6];
    const float* w3  = (const float*)d_in[7];
    const float* b3  = (const float*)d_in[8];
    const float* wr1 = (const float*)d_in[9];
    const float* br1 = (const float*)d_in[10];
    const float* wr2 = (const float*)d_in[11];
    const float* br2 = (const float*)d_in[12];
    const float* wf1 = (const float*)d_in[13];
    const float* bf1 = (const float*)d_in[14];
    const float* wf2 = (const float*)d_in[15];
    const float* bf2 = (const float*)d_in[16];
    float* out = (float*)d_out;

    unsigned *X0h, *XAh;
    float *feat, *S, *wt;
    uint2 *wpk;
    cudaGetSymbolAddress((void**)&X0h, g_X0h);
    cudaGetSymbolAddress((void**)&XAh, g_XAh);
    cudaGetSymbolAddress((void**)&feat, g_feat);
    cudaGetSymbolAddress((void**)&S, g_S);
    cudaGetSymbolAddress((void**)&wt, g_wt);
    cudaGetSymbolAddress((void**)&wpk, g_wp);

    cudaFuncSetAttribute(k_conv5_v3, cudaFuncAttributeMaxDynamicSharedMemorySize, C5_TOT);
    cudaFuncSetAttribute(k_winfused, cudaFuncAttributeMaxDynamicSharedMemorySize, F_TOT);

    k_prep<<<96, 256>>>(w1, w2, w3, wr1, wr2, wf1, wf2, wt, wpk);
    k_build<<<dim3(4, NIMG), 256>>>(pos, rt, emb, X0h);
    k_conv5_v3<<<dim3(9, NIMG), 384, C5_TOT>>>(X0h, wpk, b1, XAh);
    k_winfused<<<NIMG*2, 384, F_TOT>>>(XAh, wpk + 6656, wpk + 15872, b2, b3, rt, pos, feat);
    k_room<<<NIMG, 128>>>(feat, wt, br1, br2, S);
    k_fc<<<NIMG/4, 256>>>(S, wt, bf1, bf2, out);
}

// round 16
// speedup vs baseline: 1.4252x; 1.0377x over previous
#include <cuda_runtime.h>
#include <cuda_fp16.h>
#include <cstdint>

#define NIMG 256
#define RROOM 32
#define WW 8
#define HH 6
#define MXY 72
#define PIX (MXY*MXY)
#define EMBD 6

__device__ __align__(16) unsigned g_X0h[NIMG*8*PIX];
__device__ __align__(16) unsigned g_XAh[NIMG*32*PIX];   // conv5 out, NHWC (32 half2/px)
__device__ float g_feat[NIMG*RROOM*64];
__device__ float g_S[NIMG*128];
__device__ float g_wt[122880];
__device__ __align__(16) uint2 g_wp[25088];  // conv5 @0, conv3A @6656, conv3B @15872

__device__ __forceinline__ unsigned f2h2(float lo, float hi) {
    __half2 h = __floats2half2_rn(lo, hi);
    return *reinterpret_cast<unsigned*>(&h);
}
__device__ __forceinline__ void mma_f16(float d[4], const unsigned a[4], unsigned b0, unsigned b1) {
    asm volatile("mma.sync.aligned.m16n8k16.row.col.f32.f16.f16.f32 "
        "{%0,%1,%2,%3},{%4,%5,%6,%7},{%8,%9},{%0,%1,%2,%3};"
        : "+f"(d[0]), "+f"(d[1]), "+f"(d[2]), "+f"(d[3])
        : "r"(a[0]), "r"(a[1]), "r"(a[2]), "r"(a[3]), "r"(b0), "r"(b1));
}
__device__ __forceinline__ uint32_t smem_u32(const void* p) {
    uint32_t a;
    asm("{ .reg .u64 t; cvta.to.shared.u64 t, %1; cvt.u32.u64 %0, t; }" : "=r"(a) : "l"(p));
    return a;
}
#define CP_COMMIT() asm volatile("cp.async.commit_group;" ::: "memory")
#define CP_WAIT0()  asm volatile("cp.async.wait_group 0;" ::: "memory")

__global__ void k_prep(const float* __restrict__ w1, const float* __restrict__ w2,
                       const float* __restrict__ w3,
                       const float* __restrict__ wr1, const float* __restrict__ wr2,
                       const float* __restrict__ wf1, const float* __restrict__ wf2,
                       float* __restrict__ wt, uint2* __restrict__ wp) {
    int t0 = blockIdx.x * blockDim.x + threadIdx.x;
    int stride = gridDim.x * blockDim.x;
    for (int i = t0; i < 8192; i += stride)  { int c = i >> 7, o = i & 127; wt[i]         = wr1[o*64 + c]; }
    for (int i = t0; i < 16384; i += stride) { int c = i >> 7, o = i & 127; wt[8192 + i]  = wr2[o*128 + c]; }
    for (int i = t0; i < 32768; i += stride) { int c = i >> 8, o = i & 255; wt[24576 + i] = wf1[o*128 + c]; }
    for (int i = t0; i < 65536; i += stride) { int c = i >> 8, o = i & 255; wt[57344 + i] = wf2[o*256 + c]; }
    for (int i = t0; i < 6656; i += stride) {
        int lane = i & 31, rest = i >> 5;
        int o = rest & 7; rest >>= 3;
        int ks = rest % 13, cc = rest / 13;
        int gg = lane >> 2, tt = lane & 3;
        int oc = o*8 + gg, ic0 = cc*8 + 2*tt;
        int tap0 = 2*ks, tap1 = 2*ks + 1;
        uint2 pv;
        pv.x = f2h2(w1[oc*400 + ic0*25 + tap0], w1[oc*400 + (ic0+1)*25 + tap0]);
        pv.y = (tap1 < 25) ? f2h2(w1[oc*400 + ic0*25 + tap1], w1[oc*400 + (ic0+1)*25 + tap1]) : 0u;
        wp[i] = pv;
    }
    for (int i = t0; i < 9216; i += stride) {
        int lane = i & 31, rest = i >> 5;
        int o = rest & 7; rest >>= 3;
        int ks = rest % 9, cc = rest / 9;
        int gg = lane >> 2, tt = lane & 3;
        int oc = o*8 + gg;
        int icA = cc*16 + 2*tt, icB = cc*16 + 2*tt + 8;
        uint2 pv, qv;
        pv.x = f2h2(w2[oc*576 + icA*9 + ks], w2[oc*576 + (icA+1)*9 + ks]);
        pv.y = f2h2(w2[oc*576 + icB*9 + ks], w2[oc*576 + (icB+1)*9 + ks]);
        wp[6656 + i] = pv;
        qv.x = f2h2(w3[oc*576 + icA*9 + ks], w3[oc*576 + (icA+1)*9 + ks]);
        qv.y = f2h2(w3[oc*576 + icB*9 + ks], w3[oc*576 + (icB+1)*9 + ks]);
        wp[15872 + i] = qv;
    }
}

__global__ void k_build(const int* __restrict__ pos, const float* __restrict__ rt,
                        const float* __restrict__ emb, unsigned* __restrict__ X0h) {
    int n = blockIdx.y, q = blockIdx.x, t = threadIdx.x;
    __shared__ int s_px[RROOM], s_py[RROOM];
    __shared__ float s_emb[RROOM*EMBD];
    if (t < RROOM) { s_px[t] = pos[(n*RROOM+t)*2]; s_py[t] = pos[(n*RROOM+t)*2+1]; }
    if (t < RROOM*EMBD) s_emb[t] = emb[t];
    __syncthreads();
    int p0 = q * 1296, p1 = p0 + 1296;
    for (int pix = p0 + t; pix < p1; pix += blockDim.x) {
        int i = pix / MXY, j = pix % MXY;
        float acc[9], em[EMBD];
        #pragma unroll
        for (int c = 0; c < 9; c++) acc[c] = 0.f;
        #pragma unroll
        for (int e = 0; e < EMBD; e++) em[e] = 0.f;
        #pragma unroll 1
        for (int r = 0; r < RROOM; r++) {
            int w = i - s_px[r], h = j - s_py[r];
            if ((unsigned)w < (unsigned)WW && (unsigned)h < (unsigned)HH) {
                const float* rp = rt + (r*9)*(WW*HH) + w*HH + h;
                float m0 = rp[0];
                #pragma unroll
                for (int c = 0; c < 9; c++) acc[c] += rp[c*(WW*HH)];
                #pragma unroll
                for (int e = 0; e < EMBD; e++) em[e] += s_emb[r*EMBD+e] * m0;
            }
        }
        unsigned* xp = X0h + (size_t)n*8*PIX + pix;
        xp[0*PIX] = f2h2(acc[0], acc[1]);
        xp[1*PIX] = f2h2(acc[2], acc[3]);
        xp[2*PIX] = f2h2(acc[4], acc[5]);
        xp[3*PIX] = f2h2(acc[6], acc[7]);
        xp[4*PIX] = f2h2(acc[8], 1.0f);
        xp[5*PIX] = f2h2(em[0], em[1]);
        xp[6*PIX] = f2h2(em[2], em[3]);
        xp[7*PIX] = f2h2(em[4], em[5]);
    }
}

// conv5 16->64, ReLU, NHWC out. Epilogue staged through smem for coalesced STG.
#define C5_A 53248
#define C5_TOT 82944
__global__ __launch_bounds__(384, 1)
void k_conv5_v3(const unsigned* __restrict__ in, const uint2* __restrict__ wp,
                const float* __restrict__ bias, unsigned* __restrict__ out) {
    extern __shared__ __align__(16) char smem[];
    uint32_t sb = smem_u32(smem);
    int t = threadIdx.x, warp = t >> 5, lane = t & 31;
    int g = lane >> 2, tig = lane & 3;
    int n = blockIdx.y, r0 = blockIdx.x * 8;
    const uint2* swf = (const uint2*)smem;
    const unsigned* sx = (const unsigned*)(smem + C5_A);
    const unsigned* inb = in + (size_t)n * 8 * PIX;

    float acc[3][8][4];
    #pragma unroll
    for (int a = 0; a < 3; a++)
        #pragma unroll
        for (int o = 0; o < 8; o++)
            #pragma unroll
            for (int k = 0; k < 4; k++) acc[a][o][k] = 0.f;

    unsigned axoff[3][2];
    int ppix[3][2];
    #pragma unroll
    for (int t4 = 0; t4 < 3; t4++)
        #pragma unroll
        for (int gi = 0; gi < 2; gi++) {
            int p = warp*48 + t4*16 + g + gi*8;
            ppix[t4][gi] = p;
            axoff[t4][gi] = (p/72)*76 + (p%72);
        }

    #pragma unroll
    for (int jj = 0; jj < 9; jj++) {
        int i = t + jj*384;
        if (i < 3328) {
            unsigned dst = sb + (unsigned)i*16u;
            const char* src = (const char*)wp + (size_t)i*16;
            asm volatile("cp.async.cg.shared.global [%0], [%1], 16;" :: "r"(dst), "l"(src) : "memory");
        }
    }
    #pragma unroll
    for (int jj = 0; jj < 19; jj++) {
        int i = t + jj*384;
        if (i < 7296) {
            int pair = i / 912; int s = i - pair*912;
            int rr = s / 76; int cx = s - rr*76;
            int gr = r0 - 2 + rr, gc = cx - 2;
            unsigned v = ((unsigned)gr < 72u && (unsigned)gc < 72u) ? 4u : 0u;
            const unsigned* gp = inb + (size_t)pair*PIX + (v ? (gr*72 + gc) : 0);
            unsigned dst = sb + C5_A + (unsigned)i*4u;
            asm volatile("cp.async.ca.shared.global [%0], [%1], 4, %2;"
                         :: "r"(dst), "l"(gp), "r"(v) : "memory");
        }
    }
    CP_COMMIT();
    CP_WAIT0();
    __syncthreads();

    #pragma unroll 1
    for (int cc = 0; cc < 2; cc++) {
        const unsigned* sxc = sx + (cc*4 + tig)*912;
        const uint2* wfc = swf + cc*3328;
        #pragma unroll
        for (int ks = 0; ks < 13; ks++) {
            const int tap0 = 2*ks;
            const int tap1 = (2*ks + 1 < 25) ? (2*ks + 1) : 24;
            const int off0 = (tap0/5)*76 + (tap0%5);
            const int off1 = (tap1/5)*76 + (tap1%5);
            unsigned av[3][4];
            #pragma unroll
            for (int t4 = 0; t4 < 3; t4++)
                #pragma unroll
                for (int gi = 0; gi < 2; gi++) {
                    av[t4][gi]     = sxc[axoff[t4][gi] + off0];
                    av[t4][2 + gi] = sxc[axoff[t4][gi] + off1];
                }
            #pragma unroll
            for (int o = 0; o < 8; o++) {
                uint2 b = wfc[ks*256 + o*32 + lane];
                mma_f16(acc[0][o], av[0], b.x, b.y);
                mma_f16(acc[1][o], av[1], b.x, b.y);
                mma_f16(acc[2][o], av[2], b.x, b.y);
            }
        }
    }

    // staged NHWC epilogue: smem (36-word px stride) -> coalesced 16B STG
    __syncthreads();
    unsigned* stg = (unsigned*)smem;
    #pragma unroll
    for (int o = 0; o < 8; o++) {
        int oc0 = o*8 + 2*tig;
        float bv0 = bias[oc0], bv1 = bias[oc0 + 1];
        #pragma unroll
        for (int t4 = 0; t4 < 3; t4++)
            #pragma unroll
            for (int gi = 0; gi < 2; gi++) {
                int p = ppix[t4][gi];
                float v0 = fmaxf(acc[t4][o][gi*2 + 0] + bv0, 0.f);
                float v1 = fmaxf(acc[t4][o][gi*2 + 1] + bv1, 0.f);
                stg[p*36 + o*4 + tig] = f2h2(v0, v1);
            }
    }
    __syncthreads();
    unsigned* outb = out + (size_t)n * 32 * PIX;
    #pragma unroll
    for (int jj = 0; jj < 12; jj++) {
        int u = t + jj*384;          // 4608 = 576px x 8 quads
        int p = u >> 3, q = u & 7;
        int gr = r0 + p/72, gc = p%72;
        uint4 v = *(const uint4*)(stg + p*36 + q*4);
        *(uint4*)(outb + (size_t)(gr*72 + gc)*32 + q*4) = v;
    }
}

// ---------------------------------------------------------------------------
// FUSED layers 2+3 + feat, windowed; gather for chunk ch+1 pipelined under
// L3 compute of chunk ch (IN buffer is dead after the post-L2 barrier).
// smem: W2 @0 (73728), W3 @73728, IN @147456 (34560), WIN @182016 (23040).
// ---------------------------------------------------------------------------
#define F_W3 73728
#define F_IN 147456
#define F_WIN 182016
#define F_TOT 205056
__global__ __launch_bounds__(384, 1)
void k_winfused(const unsigned* __restrict__ xa, const uint2* __restrict__ wp2,
                const uint2* __restrict__ wp3,
                const float* __restrict__ bias2, const float* __restrict__ bias3,
                const float* __restrict__ rt, const int* __restrict__ pos,
                float* __restrict__ feat) {
    extern __shared__ __align__(16) char smem[];
    __shared__ float s_feat[2][64];
    __shared__ float s_wm[16][48];
    __shared__ float s_rsum[16];
    __shared__ int s_pos[16][2];
    uint32_t sb = smem_u32(smem);
    int t = threadIdx.x, warp = t >> 5, lane = t & 31;
    int g = lane >> 2, tig = lane & 3;
    int bx = blockIdx.x, n = bx >> 1, rbase = (bx & 1) * 16;
    const uint2* swf2 = (const uint2*)smem;
    const uint2* swf3 = (const uint2*)(smem + F_W3);
    const unsigned* INs = (const unsigned*)(smem + F_IN);
    unsigned* WINs = (unsigned*)(smem + F_WIN);
    const unsigned* xan = xa + (size_t)n * 32 * PIX;

    for (int i = t; i < 16*48; i += 384) {
        int rr = i / 48, k = i % 48;
        s_wm[rr][k] = rt[(rbase + rr)*432 + k];
    }
    if (t < 32) s_pos[t >> 1][t & 1] = pos[(n*RROOM + rbase + (t >> 1))*2 + (t & 1)];
    if (t < 128) s_feat[t >> 6][t & 63] = 0.f;

    // both weight sets: 9216 x 16B
    #pragma unroll
    for (int jj = 0; jj < 12; jj++) {
        int i = t + jj*384;
        asm volatile("cp.async.cg.shared.global [%0], [%1], 16;"
                     :: "r"(sb + (unsigned)i*16u), "l"((const char*)wp2 + (size_t)i*16) : "memory");
    }
    #pragma unroll
    for (int jj = 0; jj < 12; jj++) {
        int i = t + jj*384;
        asm volatile("cp.async.cg.shared.global [%0], [%1], 16;"
                     :: "r"(sb + F_W3 + (unsigned)i*16u), "l"((const char*)wp3 + (size_t)i*16) : "memory");
    }
    __syncthreads();   // s_pos visible for gather
    if (t < 16) {
        float s = 0.f;
        #pragma unroll
        for (int k = 0; k < 48; k++) s += s_wm[t][k];
        s_rsum[t] = s;
    }

    // gather macro: 2 rooms x 12x10 px x 8 quads = 1920 units
    #define F_GATHER(ch) do { \
        _Pragma("unroll") \
        for (int jj = 0; jj < 5; jj++) { \
            int i = t + jj*384; \
            int rr = i / 960; int rem = i - rr*960; \
            int wr2 = rem / 80; int u = rem - wr2*80; \
            int pc = u >> 3, q = u & 7; \
            int gr = s_pos[(ch)*2 + rr][0] - 2 + wr2; \
            int gc = s_pos[(ch)*2 + rr][1] - 2 + pc; \
            unsigned v = ((unsigned)gr < 72u && (unsigned)gc < 72u) ? 16u : 0u; \
            const unsigned* gp = xan + (v ? ((size_t)(gr*72 + gc)*32 + q*4) : 0); \
            unsigned dst = sb + F_IN + (unsigned)(rr*4320 + wr2*360 + pc*36 + q*4)*4u; \
            asm volatile("cp.async.cg.shared.global [%0], [%1], 16, %2;" \
                         :: "r"(dst), "l"(gp), "r"(v) : "memory"); \
        } } while (0)

    // warp roles
    int rw2 = warp / 6, mt6 = warp % 6;              // L2: room, m16-tile of 96px
    int pp2[2];
    unsigned aw2[2];
    #pragma unroll
    for (int gi = 0; gi < 2; gi++) {
        int p = mt6*16 + g + gi*8;                   // 0..95
        pp2[gi] = p;
        int pc96 = p < 80 ? p : 79;
        aw2[gi] = (unsigned)(rw2*4320 + (pc96 >> 3)*360 + (pc96 & 7)*36 + tig);
    }
    int rw3 = warp / 6, sub3 = warp % 6;             // L3: room, (mt, oc-half)
    int mt3 = sub3 >> 1, half3 = sub3 & 1;
    int p0 = mt3*16 + g, p1 = p0 + 8;                // 0..47
    unsigned aw0 = (unsigned)(rw3*2880 + (p0/6)*288 + (p0%6)*36 + tig);
    unsigned aw1 = (unsigned)(rw3*2880 + (p1/6)*288 + (p1%6)*36 + tig);

    float bse2[8], bso2[8];
    #pragma unroll
    for (int o = 0; o < 8; o++) { bse2[o] = bias2[o*8 + 2*tig]; bso2[o] = bias2[o*8 + 2*tig + 1]; }
    float bse3[4], bso3[4];
    #pragma unroll
    for (int o = 0; o < 4; o++) {
        bse3[o] = bias3[(half3*4 + o)*8 + 2*tig];
        bso3[o] = bias3[(half3*4 + o)*8 + 2*tig + 1];
    }

    // prologue: gather chunk 0 (weights still in flight in same cp.async queue)
    F_GATHER(0);
    CP_COMMIT();
    CP_WAIT0();
    __syncthreads();

    #pragma unroll 1
    for (int ch = 0; ch < 8; ch++) {
        // ---- L2 conv3 (reads INs) ----
        float acc2[8][4];
        #pragma unroll
        for (int o = 0; o < 8; o++)
            #pragma unroll
            for (int k = 0; k < 4; k++) acc2[o][k] = 0.f;
        #pragma unroll 1
        for (int cc = 0; cc < 4; cc++) {
            const uint2* wfc = swf2 + cc*2304;
            #pragma unroll
            for (int ks = 0; ks < 9; ks++) {
                const int off = (ks/3)*360 + (ks%3)*36 + cc*8;
                unsigned av[4];
                av[0] = INs[aw2[0] + off];
                av[1] = INs[aw2[1] + off];
                av[2] = INs[aw2[0] + off + 4];
                av[3] = INs[aw2[1] + off + 4];
                #pragma unroll
                for (int o = 0; o < 8; o++) {
                    uint2 b = wfc[ks*256 + o*32 + lane];
                    mma_f16(acc2[o], av, b.x, b.y);
                }
            }
        }
        // window store (smem), zero for out-of-image pixels
        {
            int prw = s_pos[ch*2 + rw2][0], pcl = s_pos[ch*2 + rw2][1];
            #pragma unroll
            for (int gi = 0; gi < 2; gi++) {
                int p = pp2[gi];
                if (p < 80) {
                    int gr = prw - 1 + (p >> 3);
                    int gc = pcl - 1 + (p & 7);
                    bool vld = ((unsigned)gr < 72u) && ((unsigned)gc < 72u);
                    #pragma unroll
                    for (int o = 0; o < 8; o++) {
                        float v0 = vld ? fmaxf(acc2[o][gi*2 + 0] + bse2[o], 0.f) : 0.f;
                        float v1 = vld ? fmaxf(acc2[o][gi*2 + 1] + bso2[o], 0.f) : 0.f;
                        WINs[rw2*2880 + p*36 + o*4 + tig] = f2h2(v0, v1);
                    }
                }
            }
        }
        __syncthreads();   // WIN visible; IN fully consumed

        // ---- pipelined gather for ch+1 (hides under L3) ----
        if (ch < 7) {
            F_GATHER(ch + 1);
            CP_COMMIT();
        }

        // ---- L3 conv3 + pooled feat ----
        float acc3[4][4];
        #pragma unroll
        for (int o = 0; o < 4; o++)
            #pragma unroll
            for (int k = 0; k < 4; k++) acc3[o][k] = 0.f;
        #pragma unroll 1
        for (int cc = 0; cc < 4; cc++) {
            const uint2* wfc = swf3 + cc*2304;
            #pragma unroll
            for (int ks = 0; ks < 9; ks++) {
                const int off = (ks/3)*288 + (ks%3)*36 + cc*8;
                unsigned av[4];
                av[0] = WINs[aw0 + off];
                av[1] = WINs[aw1 + off];
                av[2] = WINs[aw0 + off + 4];
                av[3] = WINs[aw1 + off + 4];
                #pragma unroll
                for (int o = 0; o < 4; o++) {
                    uint2 b = wfc[ks*256 + (half3*4 + o)*32 + lane];
                    mma_f16(acc3[o], av, b.x, b.y);
                }
            }
        }
        float wm0 = s_wm[ch*2 + rw3][p0];
        float wm1 = s_wm[ch*2 + rw3][p1];
        #pragma unroll
        for (int o = 0; o < 4; o++) {
            float e = fmaxf(acc3[o][0] + bse3[o], 0.f)*wm0 + fmaxf(acc3[o][2] + bse3[o], 0.f)*wm1;
            float d2 = fmaxf(acc3[o][1] + bso3[o], 0.f)*wm0 + fmaxf(acc3[o][3] + bso3[o], 0.f)*wm1;
            e += __shfl_xor_sync(0xffffffffu, e, 16);
            e += __shfl_xor_sync(0xffffffffu, e, 8);
            e += __shfl_xor_sync(0xffffffffu, e, 4);
            d2 += __shfl_xor_sync(0xffffffffu, d2, 16);
            d2 += __shfl_xor_sync(0xffffffffu, d2, 8);
            d2 += __shfl_xor_sync(0xffffffffu, d2, 4);
            if (g == 0) {
                atomicAdd(&s_feat[rw3][(half3*4 + o)*8 + 2*tig], e);
                atomicAdd(&s_feat[rw3][(half3*4 + o)*8 + 2*tig + 1], d2);
            }
        }
        __syncthreads();
        if (t < 128) {
            int rr = t >> 6, oc = t & 63;
            feat[(n*RROOM + rbase + ch*2 + rr)*64 + oc] = s_feat[rr][oc] / s_rsum[ch*2 + rr];
            s_feat[rr][oc] = 0.f;
        }
        if (ch < 7) CP_WAIT0();
        __syncthreads();
    }
    #undef F_GATHER
}

__global__ __launch_bounds__(128)
void k_room(const float* __restrict__ feat, const float* __restrict__ wt,
            const float* __restrict__ b1, const float* __restrict__ b2,
            float* __restrict__ S) {
    const float* w1t = wt;
    const float* w2t = wt + 8192;
    int n = blockIdx.x, o = threadIdx.x;
    __shared__ float s_f[4][64];
    __shared__ float s_h1[4][128];
    float accS = 0.f;
    float bb1 = b1[o], bb2 = b2[o];
    for (int rg = 0; rg < 8; rg++) {
        #pragma unroll
        for (int i = o; i < 256; i += 128) {
            int r = i >> 6, c = i & 63;
            s_f[r][c] = feat[(n*RROOM + rg*4 + r)*64 + c];
        }
        __syncthreads();
        float a0 = bb1, a1 = bb1, a2 = bb1, a3 = bb1;
        #pragma unroll
        for (int c = 0; c < 64; c++) {
            float wv = w1t[c*128 + o];
            a0 += wv * s_f[0][c]; a1 += wv * s_f[1][c];
            a2 += wv * s_f[2][c]; a3 += wv * s_f[3][c];
        }
        s_h1[0][o] = fmaxf(a0, 0.f); s_h1[1][o] = fmaxf(a1, 0.f);
        s_h1[2][o] = fmaxf(a2, 0.f); s_h1[3][o] = fmaxf(a3, 0.f);
        __syncthreads();
        float z0 = bb2, z1 = bb2, z2 = bb2, z3 = bb2;
        #pragma unroll
        for (int c = 0; c < 128; c++) {
            float wv = w2t[c*128 + o];
            z0 += wv * s_h1[0][c]; z1 += wv * s_h1[1][c];
            z2 += wv * s_h1[2][c]; z3 += wv * s_h1[3][c];
        }
        accS += fmaxf(z0, 0.f) + fmaxf(z1, 0.f) + fmaxf(z2, 0.f) + fmaxf(z3, 0.f);
        __syncthreads();
    }
    S[n*128 + o] = accS;
}

__global__ __launch_bounds__(256)
void k_fc(const float* __restrict__ S, const float* __restrict__ wt,
          const float* __restrict__ bf1, const float* __restrict__ bf2,
          float* __restrict__ out) {
    const float* wf1t = wt + 24576;
    const float* wf2t = wt + 57344;
    int n0 = blockIdx.x * 4, o = threadIdx.x;
    __shared__ float s_in[4][128];
    __shared__ float s_h[4][256];
    #pragma unroll
    for (int i = o; i < 512; i += 256) {
        int q = i >> 7, c = i & 127;
        s_in[q][c] = S[(n0 + q)*128 + c];
    }
    __syncthreads();
    float a0 = bf1[o], a1 = a0, a2 = a0, a3 = a0;
    #pragma unroll
    for (int c = 0; c < 128; c++) {
        float wv = wf1t[c*256 + o];
        a0 += wv * s_in[0][c]; a1 += wv * s_in[1][c];
        a2 += wv * s_in[2][c]; a3 += wv * s_in[3][c];
    }
    s_h[0][o] = fmaxf(a0, 0.f); s_h[1][o] = fmaxf(a1, 0.f);
    s_h[2][o] = fmaxf(a2, 0.f); s_h[3][o] = fmaxf(a3, 0.f);
    __syncthreads();
    float z0 = bf2[o], z1 = z0, z2 = z0, z3 = z0;
    #pragma unroll
    for (int c = 0; c < 256; c++) {
        float wv = wf2t[c*256 + o];
        z0 += wv * s_h[0][c]; z1 += wv * s_h[1][c];
        z2 += wv * s_h[2][c]; z3 += wv * s_h[3][c];
    }
    out[(n0 + 0)*256 + o] = z0;
    out[(n0 + 1)*256 + o] = z1;
    out[(n0 + 2)*256 + o] = z2;
    out[(n0 + 3)*256 + o] = z3;
}

extern "C" void kernel_launch(void* const* d_in, const int* in_sizes, int n_in,
                              void* d_out, int out_size) {
    const int*   pos = (const int*)d_in[0];
    const float* rt  = (const float*)d_in[1];
    const float* emb = (const float*)d_in[2];
    const float* w1  = (const float*)d_in[3];
    const float* b1  = (const float*)d_in[4];
    const float* w2  = (const float*)d_in[5];
    const float* b2  = (const float*)d_in[6];
    const float* w3  = (const float*)d_in[7];
    const float* b3  = (const float*)d_in[8];
    const float* wr1 = (const float*)d_in[9];
    const float* br1 = (const float*)d_in[10];
    const float* wr2 = (const float*)d_in[11];
    const float* br2 = (const float*)d_in[12];
    const float* wf1 = (const float*)d_in[13];
    const float* bf1 = (const float*)d_in[14];
    const float* wf2 = (const float*)d_in[15];
    const float* bf2 = (const float*)d_in[16];
    float* out = (float*)d_out;

    unsigned *X0h, *XAh;
    float *feat, *S, *wt;
    uint2 *wpk;
    cudaGetSymbolAddress((void**)&X0h, g_X0h);
    cudaGetSymbolAddress((void**)&XAh, g_XAh);
    cudaGetSymbolAddress((void**)&feat, g_feat);
    cudaGetSymbolAddress((void**)&S, g_S);
    cudaGetSymbolAddress((void**)&wt, g_wt);
    cudaGetSymbolAddress((void**)&wpk, g_wp);

    cudaFuncSetAttribute(k_conv5_v3, cudaFuncAttributeMaxDynamicSharedMemorySize, C5_TOT);
    cudaFuncSetAttribute(k_winfused, cudaFuncAttributeMaxDynamicSharedMemorySize, F_TOT);

    k_prep<<<96, 256>>>(w1, w2, w3, wr1, wr2, wf1, wf2, wt, wpk);
    k_build<<<dim3(4, NIMG), 256>>>(pos, rt, emb, X0h);
    k_conv5_v3<<<dim3(9, NIMG), 384, C5_TOT>>>(X0h, wpk, b1, XAh);
    k_winfused<<<NIMG*2, 384, F_TOT>>>(XAh, wpk + 6656, wpk + 15872, b2, b3, rt, pos, feat);
    k_room<<<NIMG, 128>>>(feat, wt, br1, br2, S);
    k_fc<<<NIMG/4, 256>>>(S, wt, bf1, bf2, out);
}